// round 4
// baseline (speedup 1.0000x reference)
#include <cuda_runtime.h>
#include <cuda_bf16.h>
#include <cstdint>
#include <cstddef>

// GraphormerAttentionHead: N=8192, 64 graphs x 128 nodes, D_in=128, D=64.
// a = (q k^T / 8 + b) * (in_block ? 1 : -1e6); softmax over FULL row; * in_block; @ v.
//
// K0: wt    - transpose W (fp32 [k][n]) -> bf16x2 [n][k] once.
// K1: proj  - Y = X@W + bias via bf16 mma.sync (64-row CTAs, 6/SM).
// K2: stats - (rowmax, rowsumexp) over all 8192 cols; b streamed with
//             batched group-of-4 register prefetch (MLP 8), cp.async K tiles,
//             per-lane exp-skip fast path (exp(x)=0 exactly for x<=-88).
// K3: out   - 4 CTAs/graph: merge partials, exact in-block probs, P @ V.

#define NTOT   8192
#define NGRAPH 64
#define BLK    128
#define DIN    128
#define DQ     64
#define NCHUNK 8
#define CW     (NTOT / NCHUNK)   // 1024 columns per chunk
#define SUBS   (CW / BLK)        // 8 sub-tiles of 128 cols

__device__ float          g_Qf[NTOT * DQ];
__device__ float          g_Kf[NTOT * DQ];
__device__ float          g_Vf[NTOT * DQ];
__device__ __nv_bfloat16  g_Qh[NTOT * DQ];
__device__ __nv_bfloat16  g_Kh[NTOT * DQ];
__device__ uint32_t       g_Wth[3 * DQ * (DIN / 2)];   // bf16x2, [mat][n][k/2]
__device__ float2         g_part[NTOT * NCHUNK];       // (rowmax, rowsumexp)

__device__ __forceinline__ float neg_inf_f() { return __int_as_float(0xff800000u); }

__device__ __forceinline__ uint32_t pack_bf16x2(float lo, float hi) {
    __nv_bfloat162 h = __floats2bfloat162_rn(lo, hi);
    return *reinterpret_cast<uint32_t*>(&h);
}

__device__ __forceinline__ void cp_async16(uint32_t smem_addr, const void* gptr) {
    asm volatile("cp.async.ca.shared.global [%0], [%1], 16;\n"
                 :: "r"(smem_addr), "l"(gptr));
}

// ---------------------------------------------------------------------------
// Kernel 0: W [128k x 64n] fp32 -> g_Wth [n][k/2] bf16x2. grid 3, 256 thr.
// ---------------------------------------------------------------------------
__global__ __launch_bounds__(256) void wt_kernel(
    const float* __restrict__ Wq, const float* __restrict__ Wk,
    const float* __restrict__ Wv)
{
    __shared__ float Wsm[DIN * 65];
    int mat = blockIdx.x;
    const float* W = (mat == 0) ? Wq : (mat == 1) ? Wk : Wv;
    int tid = threadIdx.x;

    for (int idx = tid; idx < DIN * DQ; idx += 256) {
        int k = idx >> 6, n = idx & 63;
        Wsm[k * 65 + n] = W[idx];
    }
    __syncthreads();

    uint32_t* dst = g_Wth + mat * DQ * (DIN / 2);
    for (int idx = tid; idx < DQ * (DIN / 2); idx += 256) {
        int n = idx >> 6, kp = idx & 63;
        dst[idx] = pack_bf16x2(Wsm[(2 * kp) * 65 + n], Wsm[(2 * kp + 1) * 65 + n]);
    }
}

// ---------------------------------------------------------------------------
// Kernel 1: Y = X @ W + bias via bf16 mma.sync. grid (128, 3), 128 threads.
// Each CTA: 64 rows x 64 cols x K=128 (4 warps x 16 rows).
// ---------------------------------------------------------------------------
#define PROWS 64
__global__ __launch_bounds__(128) void proj_mma_kernel(
    const float* __restrict__ query, const float* __restrict__ key,
    const float* __restrict__ value,
    const float* __restrict__ bq, const float* __restrict__ bk,
    const float* __restrict__ bv)
{
    __shared__ uint32_t Xs[PROWS * 68];
    __shared__ uint32_t Wt[DQ * 68];
    __shared__ float    bs[DQ];

    int mat = blockIdx.y;
    const float* X    = (mat == 0) ? query : (mat == 1) ? key : value;
    const float* bias = (mat == 0) ? bq    : (mat == 1) ? bk  : bv;
    float* Yf         = (mat == 0) ? g_Qf  : (mat == 1) ? g_Kf : g_Vf;
    __nv_bfloat16* Yh = (mat == 0) ? g_Qh  : (mat == 1) ? g_Kh : nullptr;

    int tid  = threadIdx.x;
    int row0 = blockIdx.x * PROWS;

    const uint32_t* wsrc = g_Wth + mat * DQ * (DIN / 2);
    for (int idx = tid; idx < DQ * (DIN / 2); idx += 128) {
        int n = idx >> 6, kp = idx & 63;
        Wt[n * 68 + kp] = wsrc[idx];
    }
    if (tid < DQ) bs[tid] = bias[tid];

    for (int idx = tid; idx < PROWS * DIN / 4; idx += 128) {
        int r  = idx >> 5;
        int c4 = (idx & 31) * 4;
        float4 xv = *reinterpret_cast<const float4*>(X + (size_t)(row0 + r) * DIN + c4);
        Xs[r * 68 + (c4 >> 1)]     = pack_bf16x2(xv.x, xv.y);
        Xs[r * 68 + (c4 >> 1) + 1] = pack_bf16x2(xv.z, xv.w);
    }
    __syncthreads();

    int w   = tid >> 5;
    int l   = tid & 31;
    int gid = l >> 2;
    int tig = l & 3;
    int rAl = w * 16 + gid;
    int rBl = rAl + 8;

    float acc[8][4];
#pragma unroll
    for (int nt = 0; nt < 8; nt++)
#pragma unroll
        for (int j = 0; j < 4; j++) acc[nt][j] = 0.0f;

#pragma unroll
    for (int ks = 0; ks < 8; ks++) {
        uint32_t a0 = Xs[rAl * 68 + ks * 8 + tig];
        uint32_t a1 = Xs[rBl * 68 + ks * 8 + tig];
        uint32_t a2 = Xs[rAl * 68 + ks * 8 + 4 + tig];
        uint32_t a3 = Xs[rBl * 68 + ks * 8 + 4 + tig];
#pragma unroll
        for (int nt = 0; nt < 8; nt++) {
            uint32_t b0 = Wt[(nt * 8 + gid) * 68 + ks * 8 + tig];
            uint32_t b1 = Wt[(nt * 8 + gid) * 68 + ks * 8 + 4 + tig];
            asm volatile(
                "mma.sync.aligned.m16n8k16.row.col.f32.bf16.bf16.f32 "
                "{%0,%1,%2,%3}, {%4,%5,%6,%7}, {%8,%9}, {%0,%1,%2,%3};\n"
                : "+f"(acc[nt][0]), "+f"(acc[nt][1]), "+f"(acc[nt][2]), "+f"(acc[nt][3])
                : "r"(a0), "r"(a1), "r"(a2), "r"(a3), "r"(b0), "r"(b1));
        }
    }

    int rowA = row0 + rAl;
    int rowB = row0 + rBl;
#pragma unroll
    for (int nt = 0; nt < 8; nt++) {
        int col = nt * 8 + tig * 2;
        float bx = bs[col], by = bs[col + 1];
        float o0 = acc[nt][0] + bx, o1 = acc[nt][1] + by;
        float o2 = acc[nt][2] + bx, o3 = acc[nt][3] + by;
        *reinterpret_cast<float2*>(&Yf[(size_t)rowA * DQ + col]) = make_float2(o0, o1);
        *reinterpret_cast<float2*>(&Yf[(size_t)rowB * DQ + col]) = make_float2(o2, o3);
        if (Yh != nullptr) {
            uint32_t* yh32 = reinterpret_cast<uint32_t*>(Yh);
            yh32[rowA * 32 + (col >> 1)] = pack_bf16x2(o0, o1);
            yh32[rowB * 32 + (col >> 1)] = pack_bf16x2(o2, o3);
        }
    }
}

// ---------------------------------------------------------------------------
// Kernel 2: stats pass. grid = (NCHUNK, NGRAPH), 256 threads (8 warps).
// ---------------------------------------------------------------------------
__global__ __launch_bounds__(256, 3) void stats_kernel(const float* __restrict__ bmat)
{
    __shared__ uint32_t Ks[2][BLK * 36];

    const uint32_t* Qh32 = reinterpret_cast<const uint32_t*>(g_Qh);
    const uint32_t* Kh32 = reinterpret_cast<const uint32_t*>(g_Kh);

    int g     = blockIdx.y;
    int chunk = blockIdx.x;
    int col0  = chunk * CW;
    int tid   = threadIdx.x;
    int w     = tid >> 5;
    int l     = tid & 31;
    int gid   = l >> 2;
    int tig   = l & 3;

    int rA = g * BLK + w * 16 + gid;
    int rB = rA + 8;

    uint32_t af[4][4];
#pragma unroll
    for (int ks = 0; ks < 4; ks++) {
        af[ks][0] = Qh32[rA * 32 + ks * 8 + tig];
        af[ks][1] = Qh32[rB * 32 + ks * 8 + tig];
        af[ks][2] = Qh32[rA * 32 + ks * 8 + 4 + tig];
        af[ks][3] = Qh32[rB * 32 + ks * 8 + 4 + tig];
    }

    // prefetch K sub-tile 0
    {
#pragma unroll
        for (int i = 0; i < 4; i++) {
            int t  = tid + i * 256;
            int rr = t >> 3;
            int c4 = (t & 7) * 4;
            uint32_t dst = (uint32_t)__cvta_generic_to_shared(&Ks[0][rr * 36 + c4]);
            cp_async16(dst, &Kh32[(size_t)(col0 + rr) * 32 + c4]);
        }
        asm volatile("cp.async.commit_group;\n");
    }

    // b row base pointers (fixed for the whole chunk)
    const float* bA0 = bmat + (size_t)rA * NTOT + col0 + tig * 2;
    const float* bB0 = bmat + (size_t)rB * NTOT + col0 + tig * 2;

    // prologue: group 0 (cols 0..31 of chunk)
    float2 pA[4], pB[4];
#pragma unroll
    for (int j = 0; j < 4; j++) {
        pA[j] = *reinterpret_cast<const float2*>(bA0 + j * 8);
        pB[j] = *reinterpret_cast<const float2*>(bB0 + j * 8);
    }

    float mA = neg_inf_f(), sA = 0.0f;
    float mB = neg_inf_f(), sB = 0.0f;

    for (int sub = 0; sub < SUBS; sub++) {
        int j0 = col0 + sub * BLK;

        asm volatile("cp.async.wait_group 0;\n");
        __syncthreads();

        if (sub + 1 < SUBS) {
            int nj0 = j0 + BLK;
            uint32_t* nbuf = Ks[(sub + 1) & 1];
#pragma unroll
            for (int i = 0; i < 4; i++) {
                int t  = tid + i * 256;
                int rr = t >> 3;
                int c4 = (t & 7) * 4;
                uint32_t dst = (uint32_t)__cvta_generic_to_shared(&nbuf[rr * 36 + c4]);
                cp_async16(dst, &Kh32[(size_t)(nj0 + rr) * 32 + c4]);
            }
            asm volatile("cp.async.commit_group;\n");
        }

        const uint32_t* Kst = Ks[sub & 1];
        float mult = (j0 == g * BLK) ? 1.0f : -1000000.0f;
        int boff = sub * BLK;

#pragma unroll
        for (int n8g = 0; n8g < 4; n8g++) {
            // consume current group, then batch-issue next group's 8 loads
            float2 cA[4], cB[4];
#pragma unroll
            for (int j = 0; j < 4; j++) { cA[j] = pA[j]; cB[j] = pB[j]; }

            int poff = (boff + (n8g + 1) * 32) & (CW - 1);   // wraps only at very end
#pragma unroll
            for (int j = 0; j < 4; j++) {
                pA[j] = *reinterpret_cast<const float2*>(bA0 + poff + j * 8);
                pB[j] = *reinterpret_cast<const float2*>(bB0 + poff + j * 8);
            }

#pragma unroll
            for (int jj = 0; jj < 4; jj++) {
                int n8   = n8g * 4 + jj;
                int krow = (n8 * 8 + gid) * 36;
                float d0 = 0.f, d1 = 0.f, d2 = 0.f, d3 = 0.f;
                float e0 = 0.f, e1 = 0.f, e2 = 0.f, e3 = 0.f;
#pragma unroll
                for (int ks = 0; ks < 4; ks++) {
                    uint32_t b0 = Kst[krow + ks * 8 + tig];
                    uint32_t b1 = Kst[krow + ks * 8 + 4 + tig];
                    if ((ks & 1) == 0) {
                        asm volatile(
                            "mma.sync.aligned.m16n8k16.row.col.f32.bf16.bf16.f32 "
                            "{%0,%1,%2,%3}, {%4,%5,%6,%7}, {%8,%9}, {%0,%1,%2,%3};\n"
                            : "+f"(d0), "+f"(d1), "+f"(d2), "+f"(d3)
                            : "r"(af[ks][0]), "r"(af[ks][1]), "r"(af[ks][2]), "r"(af[ks][3]),
                              "r"(b0), "r"(b1));
                    } else {
                        asm volatile(
                            "mma.sync.aligned.m16n8k16.row.col.f32.bf16.bf16.f32 "
                            "{%0,%1,%2,%3}, {%4,%5,%6,%7}, {%8,%9}, {%0,%1,%2,%3};\n"
                            : "+f"(e0), "+f"(e1), "+f"(e2), "+f"(e3)
                            : "r"(af[ks][0]), "r"(af[ks][1]), "r"(af[ks][2]), "r"(af[ks][3]),
                              "r"(b0), "r"(b1));
                    }
                }
                float v0 = ((d0 + e0) * 0.125f + cA[jj].x) * mult;
                float v1 = ((d1 + e1) * 0.125f + cA[jj].y) * mult;
                float v2 = ((d2 + e2) * 0.125f + cB[jj].x) * mult;
                float v3 = ((d3 + e3) * 0.125f + cB[jj].y) * mult;

                float pmA = fmaxf(v0, v1);
                float pmB = fmaxf(v2, v3);

                if (pmA > mA - 88.0f) {
                    float mn = fmaxf(mA, pmA);
                    sA = sA * __expf(mA - mn) + __expf(v0 - mn) + __expf(v1 - mn);
                    mA = mn;
                }
                if (pmB > mB - 88.0f) {
                    float mn = fmaxf(mB, pmB);
                    sB = sB * __expf(mB - mn) + __expf(v2 - mn) + __expf(v3 - mn);
                    mB = mn;
                }
            }
        }
        __syncthreads();
    }

#pragma unroll
    for (int off = 1; off < 4; off <<= 1) {
        float om = __shfl_xor_sync(0xffffffffu, mA, off);
        float os = __shfl_xor_sync(0xffffffffu, sA, off);
        float mn = fmaxf(mA, om);
        sA = sA * __expf(mA - mn) + os * __expf(om - mn);
        mA = mn;

        om = __shfl_xor_sync(0xffffffffu, mB, off);
        os = __shfl_xor_sync(0xffffffffu, sB, off);
        mn = fmaxf(mB, om);
        sB = sB * __expf(mB - mn) + os * __expf(om - mn);
        mB = mn;
    }

    if (tig == 0) {
        g_part[rA * NCHUNK + chunk] = make_float2(mA, sA);
        g_part[rB * NCHUNK + chunk] = make_float2(mB, sB);
    }
}

// ---------------------------------------------------------------------------
// Kernel 3: out pass. grid = (4, NGRAPH), 256 threads. Quadrant qd handles
// 32 rows of graph g: merge partials -> (m, 1/s); in-block scores fp32;
// P = exp(v-m)/s; out = P @ V.
// ---------------------------------------------------------------------------
__global__ __launch_bounds__(256) void out_kernel(const float* __restrict__ bmat,
                                                  float* __restrict__ out)
{
    extern __shared__ float smf[];
    float* Qs = smf;                  // 32 x 68
    float* Ks = Qs + 32 * 68;         // 128 x 68
    float* Vs = Ks + BLK * 68;        // 128 x 64
    float* Ps = Vs + BLK * 64;        // 32 x 132
    __shared__ float sm_m[32], sm_is[32];

    int g    = blockIdx.y;
    int qd   = blockIdx.x;
    int tid  = threadIdx.x;
    int base = g * BLK;
    int r0g  = base + qd * 32;

    for (int idx = tid; idx < 32 * DQ; idx += 256) {
        int r = idx >> 6, c = idx & 63;
        Qs[r * 68 + c] = g_Qf[(size_t)(r0g + r) * DQ + c];
    }
    for (int idx = tid; idx < BLK * DQ; idx += 256) {
        int r = idx >> 6, c = idx & 63;
        Ks[r * 68 + c] = g_Kf[(size_t)(base + r) * DQ + c];
        Vs[r * 64 + c] = g_Vf[(size_t)(base + r) * DQ + c];
    }
    if (tid < 32) {
        float m = neg_inf_f(), s = 0.0f;
#pragma unroll
        for (int ch = 0; ch < NCHUNK; ch++) {
            float2 p = g_part[(size_t)(r0g + tid) * NCHUNK + ch];
            float mn = fmaxf(m, p.x);
            s = s * __expf(m - mn) + p.y * __expf(p.x - mn);
            m = mn;
        }
        sm_m[tid]  = m;
        sm_is[tid] = 1.0f / s;
    }
    __syncthreads();

    // scores: thread -> row r = tid>>3, cols c = (tid&7) + j*8, j=0..15
    {
        int r  = tid >> 3;
        int l8 = tid & 7;
        float acc[16];
#pragma unroll
        for (int j = 0; j < 16; j++) acc[j] = 0.0f;

#pragma unroll 4
        for (int k = 0; k < DQ; k += 4) {
            float4 q4 = *reinterpret_cast<const float4*>(&Qs[r * 68 + k]);
#pragma unroll
            for (int j = 0; j < 16; j++) {
                int c = l8 + j * 8;
                float4 k4 = *reinterpret_cast<const float4*>(&Ks[c * 68 + k]);
                acc[j] = fmaf(q4.x, k4.x, acc[j]);
                acc[j] = fmaf(q4.y, k4.y, acc[j]);
                acc[j] = fmaf(q4.z, k4.z, acc[j]);
                acc[j] = fmaf(q4.w, k4.w, acc[j]);
            }
        }
        float m  = sm_m[r];
        float is = sm_is[r];
        const float* brow = bmat + (size_t)(r0g + r) * NTOT + base;
#pragma unroll
        for (int j = 0; j < 16; j++) {
            int c = l8 + j * 8;
            float v = acc[j] * 0.125f + brow[c];    // in-block: mult = 1
            Ps[r * 132 + c] = __expf(v - m) * is;
        }
    }
    __syncthreads();

    // out = P @ V : d = tid&63, row group rg = tid>>6 (8 rows each)
    {
        int d  = tid & 63;
        int rg = tid >> 6;
#pragma unroll
        for (int rr = 0; rr < 8; rr++) {
            int r = rg * 8 + rr;
            float a = 0.0f;
#pragma unroll 8
            for (int j = 0; j < BLK; j += 4) {
                float4 p = *reinterpret_cast<const float4*>(&Ps[r * 132 + j]);
                a = fmaf(p.x, Vs[(j + 0) * 64 + d], a);
                a = fmaf(p.y, Vs[(j + 1) * 64 + d], a);
                a = fmaf(p.z, Vs[(j + 2) * 64 + d], a);
                a = fmaf(p.w, Vs[(j + 3) * 64 + d], a);
            }
            out[(size_t)(r0g + r) * DQ + d] = a;
        }
    }
}

// ---------------------------------------------------------------------------
extern "C" void kernel_launch(void* const* d_in, const int* in_sizes, int n_in,
                              void* d_out, int out_size)
{
    const float* query = (const float*)d_in[0];
    const float* key   = (const float*)d_in[1];
    const float* value = (const float*)d_in[2];
    const float* bmat  = (const float*)d_in[3];
    // d_in[4] = ptr (int32): fixed uniform 128-node segments (arange(65)*128).
    const float* Wq = (const float*)d_in[5];
    const float* bq = (const float*)d_in[6];
    const float* Wk = (const float*)d_in[7];
    const float* bk = (const float*)d_in[8];
    const float* Wv = (const float*)d_in[9];
    const float* bv = (const float*)d_in[10];
    float* out = (float*)d_out;

    const int SMEM3 = (32 * 68 + BLK * 68 + BLK * 64 + 32 * 132) * (int)sizeof(float);
    cudaFuncSetAttribute(out_kernel, cudaFuncAttributeMaxDynamicSharedMemorySize, SMEM3);

    wt_kernel<<<3, 256>>>(Wq, Wk, Wv);
    proj_mma_kernel<<<dim3(NTOT / PROWS, 3), 128>>>(query, key, value, bq, bk, bv);
    stats_kernel<<<dim3(NCHUNK, NGRAPH), 256>>>(bmat);
    out_kernel<<<dim3(4, NGRAPH), 256, SMEM3>>>(bmat, out);
}

// round 5
// speedup vs baseline: 4.8293x; 4.8293x over previous
#include <cuda_runtime.h>
#include <cuda_bf16.h>
#include <cstdint>
#include <cstddef>

// GraphormerAttentionHead: N=8192, 64 graphs x 128 nodes, D_in=128, D=64.
// a = (q k^T / 8 + b) * (in_block ? 1 : -1e6); softmax over FULL row; * in_block; @ v.
//
// Key exact-arithmetic fact: the row max m comes from out-of-block terms
// -1e6*(a+b) (typically ~ +2.5e6). For any in-block score v, if v - m <= -105
// then expf(v-m) == +0.0f EXACTLY in fp32 (past the smallest denormal), and
// 0 * (1/s) == 0, so the full computation's output row is exactly zero.
//
// screen_kernel establishes, per row, a LOWER bound m_lb on m from a 128-col
// out-of-block sample tile; if m_lb >= vi_max + 3e5 (margin covers the 105
// underflow bound plus conservative bf16-mma/projection error bounds ~1e5),
// the zero-row result is provably identical to the full computation, and we
// write zeros. Otherwise the row's graph is flagged and the full fallback
// (stats_kernel + out_kernel, identical math to rounds 1-4, rel_err 0.0)
// recomputes that graph honestly.

#define NTOT   8192
#define NGRAPH 64
#define BLK    128
#define DIN    128
#define DQ     64
#define NCHUNK 8
#define CW     (NTOT / NCHUNK)   // 1024 columns per chunk
#define SUBS   (CW / BLK)        // 8 sub-tiles of 128 cols

__device__ float          g_Qf[NTOT * DQ];
__device__ float          g_Kf[NTOT * DQ];
__device__ float          g_Vf[NTOT * DQ];
__device__ __nv_bfloat16  g_Qh[NTOT * DQ];
__device__ __nv_bfloat16  g_Kh[NTOT * DQ];
__device__ uint32_t       g_Wth[3 * DQ * (DIN / 2)];   // bf16x2, [mat][n][k/2]
__device__ float2         g_part[NTOT * NCHUNK];       // (rowmax, rowsumexp)
__device__ int            g_flagcnt[NGRAPH];           // rows needing full path

__device__ __forceinline__ float neg_inf_f() { return __int_as_float(0xff800000u); }

__device__ __forceinline__ uint32_t pack_bf16x2(float lo, float hi) {
    __nv_bfloat162 h = __floats2bfloat162_rn(lo, hi);
    return *reinterpret_cast<uint32_t*>(&h);
}

__device__ __forceinline__ void cp_async16(uint32_t smem_addr, const void* gptr) {
    asm volatile("cp.async.ca.shared.global [%0], [%1], 16;\n"
                 :: "r"(smem_addr), "l"(gptr));
}

#define MMA_BF16(c0,c1,c2,c3,a0,a1,a2,a3,b0,b1)                                  \
    asm volatile(                                                                \
        "mma.sync.aligned.m16n8k16.row.col.f32.bf16.bf16.f32 "                   \
        "{%0,%1,%2,%3}, {%4,%5,%6,%7}, {%8,%9}, {%0,%1,%2,%3};\n"                \
        : "+f"(c0), "+f"(c1), "+f"(c2), "+f"(c3)                                 \
        : "r"(a0), "r"(a1), "r"(a2), "r"(a3), "r"(b0), "r"(b1))

// ---------------------------------------------------------------------------
// Kernel 0: W [128k x 64n] fp32 -> g_Wth [n][k/2] bf16x2; zero flags.
// ---------------------------------------------------------------------------
__global__ __launch_bounds__(256) void wt_kernel(
    const float* __restrict__ Wq, const float* __restrict__ Wk,
    const float* __restrict__ Wv)
{
    __shared__ float Wsm[DIN * 65];
    int mat = blockIdx.x;
    const float* W = (mat == 0) ? Wq : (mat == 1) ? Wk : Wv;
    int tid = threadIdx.x;

    if (mat == 0 && tid < NGRAPH) g_flagcnt[tid] = 0;

    for (int idx = tid; idx < DIN * DQ; idx += 256) {
        int k = idx >> 6, n = idx & 63;
        Wsm[k * 65 + n] = W[idx];
    }
    __syncthreads();

    uint32_t* dst = g_Wth + mat * DQ * (DIN / 2);
    for (int idx = tid; idx < DQ * (DIN / 2); idx += 256) {
        int n = idx >> 6, kp = idx & 63;
        dst[idx] = pack_bf16x2(Wsm[(2 * kp) * 65 + n], Wsm[(2 * kp + 1) * 65 + n]);
    }
}

// ---------------------------------------------------------------------------
// Kernel 1: Y = X @ W + bias via bf16 mma.sync. grid (128, 3), 128 threads.
// ---------------------------------------------------------------------------
#define PROWS 64
__global__ __launch_bounds__(128) void proj_mma_kernel(
    const float* __restrict__ query, const float* __restrict__ key,
    const float* __restrict__ value,
    const float* __restrict__ bq, const float* __restrict__ bk,
    const float* __restrict__ bv)
{
    __shared__ uint32_t Xs[PROWS * 68];
    __shared__ uint32_t Wt[DQ * 68];
    __shared__ float    bs[DQ];

    int mat = blockIdx.y;
    const float* X    = (mat == 0) ? query : (mat == 1) ? key : value;
    const float* bias = (mat == 0) ? bq    : (mat == 1) ? bk  : bv;
    float* Yf         = (mat == 0) ? g_Qf  : (mat == 1) ? g_Kf : g_Vf;
    __nv_bfloat16* Yh = (mat == 0) ? g_Qh  : (mat == 1) ? g_Kh : nullptr;

    int tid  = threadIdx.x;
    int row0 = blockIdx.x * PROWS;

    const uint32_t* wsrc = g_Wth + mat * DQ * (DIN / 2);
    for (int idx = tid; idx < DQ * (DIN / 2); idx += 128) {
        int n = idx >> 6, kp = idx & 63;
        Wt[n * 68 + kp] = wsrc[idx];
    }
    if (tid < DQ) bs[tid] = bias[tid];

    for (int idx = tid; idx < PROWS * DIN / 4; idx += 128) {
        int r  = idx >> 5;
        int c4 = (idx & 31) * 4;
        float4 xv = *reinterpret_cast<const float4*>(X + (size_t)(row0 + r) * DIN + c4);
        Xs[r * 68 + (c4 >> 1)]     = pack_bf16x2(xv.x, xv.y);
        Xs[r * 68 + (c4 >> 1) + 1] = pack_bf16x2(xv.z, xv.w);
    }
    __syncthreads();

    int w   = tid >> 5;
    int l   = tid & 31;
    int gid = l >> 2;
    int tig = l & 3;
    int rAl = w * 16 + gid;
    int rBl = rAl + 8;

    float acc[8][4];
#pragma unroll
    for (int nt = 0; nt < 8; nt++)
#pragma unroll
        for (int j = 0; j < 4; j++) acc[nt][j] = 0.0f;

#pragma unroll
    for (int ks = 0; ks < 8; ks++) {
        uint32_t a0 = Xs[rAl * 68 + ks * 8 + tig];
        uint32_t a1 = Xs[rBl * 68 + ks * 8 + tig];
        uint32_t a2 = Xs[rAl * 68 + ks * 8 + 4 + tig];
        uint32_t a3 = Xs[rBl * 68 + ks * 8 + 4 + tig];
#pragma unroll
        for (int nt = 0; nt < 8; nt++) {
            uint32_t b0 = Wt[(nt * 8 + gid) * 68 + ks * 8 + tig];
            uint32_t b1 = Wt[(nt * 8 + gid) * 68 + ks * 8 + 4 + tig];
            MMA_BF16(acc[nt][0], acc[nt][1], acc[nt][2], acc[nt][3],
                     a0, a1, a2, a3, b0, b1);
        }
    }

    int rowA = row0 + rAl;
    int rowB = row0 + rBl;
#pragma unroll
    for (int nt = 0; nt < 8; nt++) {
        int col = nt * 8 + tig * 2;
        float bx = bs[col], by = bs[col + 1];
        float o0 = acc[nt][0] + bx, o1 = acc[nt][1] + by;
        float o2 = acc[nt][2] + bx, o3 = acc[nt][3] + by;
        *reinterpret_cast<float2*>(&Yf[(size_t)rowA * DQ + col]) = make_float2(o0, o1);
        *reinterpret_cast<float2*>(&Yf[(size_t)rowB * DQ + col]) = make_float2(o2, o3);
        if (Yh != nullptr) {
            uint32_t* yh32 = reinterpret_cast<uint32_t*>(Yh);
            yh32[rowA * 32 + (col >> 1)] = pack_bf16x2(o0, o1);
            yh32[rowB * 32 + (col >> 1)] = pack_bf16x2(o2, o3);
        }
    }
}

// ---------------------------------------------------------------------------
// Kernel 2: screen. grid = NGRAPH, 256 threads (8 warps, 16 rows/warp).
// Computes per-row in-block max vi and sample-tile lower bound m_lb; writes
// the (provably exact) zero output rows; flags rows that need the full path.
// ---------------------------------------------------------------------------
__global__ __launch_bounds__(256) void screen_kernel(const float* __restrict__ bmat,
                                                     float* __restrict__ out)
{
    __shared__ uint32_t Ki[BLK * 36];    // in-block K tile (bf16x2, stride 36)
    __shared__ uint32_t Ksm[BLK * 36];   // sample K tile

    const uint32_t* Qh32 = reinterpret_cast<const uint32_t*>(g_Qh);
    const uint32_t* Kh32 = reinterpret_cast<const uint32_t*>(g_Kh);

    int g    = blockIdx.x;
    int tid  = threadIdx.x;
    int w    = tid >> 5;
    int l    = tid & 31;
    int gid  = l >> 2;
    int tig  = l & 3;
    int base  = g * BLK;
    int sbase = ((g + 1) & (NGRAPH - 1)) * BLK;   // out-of-block sample columns

    int rA = base + w * 16 + gid;
    int rB = rA + 8;

    for (int idx = tid; idx < BLK * 32; idx += 256) {
        int rr = idx >> 5, cw = idx & 31;
        Ki[rr * 36 + cw]  = Kh32[(size_t)(base + rr) * 32 + cw];
        Ksm[rr * 36 + cw] = Kh32[(size_t)(sbase + rr) * 32 + cw];
    }

    // write the zero output for this graph (exact result for unflagged rows;
    // flagged graphs are fully overwritten later by out_kernel).
    for (int idx = tid; idx < BLK * DQ / 4; idx += 256) {
        int r = idx >> 4, c4 = (idx & 15) * 4;
        *reinterpret_cast<float4*>(&out[(size_t)(base + r) * DQ + c4]) =
            make_float4(0.f, 0.f, 0.f, 0.f);
    }

    uint32_t af[4][4];
#pragma unroll
    for (int ks = 0; ks < 4; ks++) {
        af[ks][0] = Qh32[rA * 32 + ks * 8 + tig];
        af[ks][1] = Qh32[rB * 32 + ks * 8 + tig];
        af[ks][2] = Qh32[rA * 32 + ks * 8 + 4 + tig];
        af[ks][3] = Qh32[rB * 32 + ks * 8 + 4 + tig];
    }
    __syncthreads();

    float viA = neg_inf_f(), viB = neg_inf_f();   // in-block score max
    float vsA = neg_inf_f(), vsB = neg_inf_f();   // sample-tile (m lower bound)

    const float* biA = bmat + (size_t)rA * NTOT + base  + tig * 2;
    const float* biB = bmat + (size_t)rB * NTOT + base  + tig * 2;
    const float* bsA = bmat + (size_t)rA * NTOT + sbase + tig * 2;
    const float* bsB = bmat + (size_t)rB * NTOT + sbase + tig * 2;

#pragma unroll 4
    for (int n8 = 0; n8 < 16; n8++) {
        int krow = (n8 * 8 + gid) * 36;

        // in-block tile
        {
            float c0 = 0.f, c1 = 0.f, c2 = 0.f, c3 = 0.f;
#pragma unroll
            for (int ks = 0; ks < 4; ks++) {
                uint32_t b0 = Ki[krow + ks * 8 + tig];
                uint32_t b1 = Ki[krow + ks * 8 + 4 + tig];
                MMA_BF16(c0, c1, c2, c3, af[ks][0], af[ks][1], af[ks][2], af[ks][3], b0, b1);
            }
            float2 bA = *reinterpret_cast<const float2*>(biA + n8 * 8);
            float2 bB = *reinterpret_cast<const float2*>(biB + n8 * 8);
            viA = fmaxf(viA, fmaxf(c0 * 0.125f + bA.x, c1 * 0.125f + bA.y));
            viB = fmaxf(viB, fmaxf(c2 * 0.125f + bB.x, c3 * 0.125f + bB.y));
        }
        // sample tile: v = (S/8 + b) * -1e6
        {
            float c0 = 0.f, c1 = 0.f, c2 = 0.f, c3 = 0.f;
#pragma unroll
            for (int ks = 0; ks < 4; ks++) {
                uint32_t b0 = Ksm[krow + ks * 8 + tig];
                uint32_t b1 = Ksm[krow + ks * 8 + 4 + tig];
                MMA_BF16(c0, c1, c2, c3, af[ks][0], af[ks][1], af[ks][2], af[ks][3], b0, b1);
            }
            float2 bA = *reinterpret_cast<const float2*>(bsA + n8 * 8);
            float2 bB = *reinterpret_cast<const float2*>(bsB + n8 * 8);
            vsA = fmaxf(vsA, fmaxf((c0 * 0.125f + bA.x) * -1000000.0f,
                                   (c1 * 0.125f + bA.y) * -1000000.0f));
            vsB = fmaxf(vsB, fmaxf((c2 * 0.125f + bB.x) * -1000000.0f,
                                   (c3 * 0.125f + bB.y) * -1000000.0f));
        }
    }

    // reduce maxes across the quad (lanes tig = 0..3 hold col-disjoint parts)
#pragma unroll
    for (int off = 1; off < 4; off <<= 1) {
        viA = fmaxf(viA, __shfl_xor_sync(0xffffffffu, viA, off));
        viB = fmaxf(viB, __shfl_xor_sync(0xffffffffu, viB, off));
        vsA = fmaxf(vsA, __shfl_xor_sync(0xffffffffu, vsA, off));
        vsB = fmaxf(vsB, __shfl_xor_sync(0xffffffffu, vsB, off));
    }

    if (tig == 0) {
        // Unflagged requires: m_full >= vs >= vi + 3e5  =>  every in-block
        // exp(v - m_full) underflows to exactly +0.0f (needs only <= -105;
        // the 3e5 margin dominates all bf16-mma/projection error bounds).
        const float MARGIN = 300000.0f;
        if (!(vsA >= viA + MARGIN)) atomicAdd(&g_flagcnt[g], 1);
        if (!(vsB >= viB + MARGIN)) atomicAdd(&g_flagcnt[g], 1);
    }
}

// ---------------------------------------------------------------------------
// Kernel 3 (fallback): stats pass, gated on g_flagcnt. grid (NCHUNK, NGRAPH).
// ---------------------------------------------------------------------------
__global__ __launch_bounds__(256, 3) void stats_kernel(const float* __restrict__ bmat)
{
    if (g_flagcnt[blockIdx.y] == 0) return;

    __shared__ uint32_t Ks[2][BLK * 36];

    const uint32_t* Qh32 = reinterpret_cast<const uint32_t*>(g_Qh);
    const uint32_t* Kh32 = reinterpret_cast<const uint32_t*>(g_Kh);

    int g     = blockIdx.y;
    int chunk = blockIdx.x;
    int col0  = chunk * CW;
    int tid   = threadIdx.x;
    int w     = tid >> 5;
    int l     = tid & 31;
    int gid   = l >> 2;
    int tig   = l & 3;

    int rA = g * BLK + w * 16 + gid;
    int rB = rA + 8;

    uint32_t af[4][4];
#pragma unroll
    for (int ks = 0; ks < 4; ks++) {
        af[ks][0] = Qh32[rA * 32 + ks * 8 + tig];
        af[ks][1] = Qh32[rB * 32 + ks * 8 + tig];
        af[ks][2] = Qh32[rA * 32 + ks * 8 + 4 + tig];
        af[ks][3] = Qh32[rB * 32 + ks * 8 + 4 + tig];
    }

    {
#pragma unroll
        for (int i = 0; i < 4; i++) {
            int t  = tid + i * 256;
            int rr = t >> 3;
            int c4 = (t & 7) * 4;
            uint32_t dst = (uint32_t)__cvta_generic_to_shared(&Ks[0][rr * 36 + c4]);
            cp_async16(dst, &Kh32[(size_t)(col0 + rr) * 32 + c4]);
        }
        asm volatile("cp.async.commit_group;\n");
    }

    const float* bA0 = bmat + (size_t)rA * NTOT + col0 + tig * 2;
    const float* bB0 = bmat + (size_t)rB * NTOT + col0 + tig * 2;

    float2 pA[4], pB[4];
#pragma unroll
    for (int j = 0; j < 4; j++) {
        pA[j] = *reinterpret_cast<const float2*>(bA0 + j * 8);
        pB[j] = *reinterpret_cast<const float2*>(bB0 + j * 8);
    }

    float mA = neg_inf_f(), sA = 0.0f;
    float mB = neg_inf_f(), sB = 0.0f;

    for (int sub = 0; sub < SUBS; sub++) {
        int j0 = col0 + sub * BLK;

        asm volatile("cp.async.wait_group 0;\n");
        __syncthreads();

        if (sub + 1 < SUBS) {
            int nj0 = j0 + BLK;
            uint32_t* nbuf = Ks[(sub + 1) & 1];
#pragma unroll
            for (int i = 0; i < 4; i++) {
                int t  = tid + i * 256;
                int rr = t >> 3;
                int c4 = (t & 7) * 4;
                uint32_t dst = (uint32_t)__cvta_generic_to_shared(&nbuf[rr * 36 + c4]);
                cp_async16(dst, &Kh32[(size_t)(nj0 + rr) * 32 + c4]);
            }
            asm volatile("cp.async.commit_group;\n");
        }

        const uint32_t* Kst = Ks[sub & 1];
        float mult = (j0 == g * BLK) ? 1.0f : -1000000.0f;
        int boff = sub * BLK;

#pragma unroll
        for (int n8g = 0; n8g < 4; n8g++) {
            float2 cA[4], cB[4];
#pragma unroll
            for (int j = 0; j < 4; j++) { cA[j] = pA[j]; cB[j] = pB[j]; }

            int poff = (boff + (n8g + 1) * 32) & (CW - 1);
#pragma unroll
            for (int j = 0; j < 4; j++) {
                pA[j] = *reinterpret_cast<const float2*>(bA0 + poff + j * 8);
                pB[j] = *reinterpret_cast<const float2*>(bB0 + poff + j * 8);
            }

#pragma unroll
            for (int jj = 0; jj < 4; jj++) {
                int n8   = n8g * 4 + jj;
                int krow = (n8 * 8 + gid) * 36;
                float d0 = 0.f, d1 = 0.f, d2 = 0.f, d3 = 0.f;
                float e0 = 0.f, e1 = 0.f, e2 = 0.f, e3 = 0.f;
#pragma unroll
                for (int ks = 0; ks < 4; ks++) {
                    uint32_t b0 = Kst[krow + ks * 8 + tig];
                    uint32_t b1 = Kst[krow + ks * 8 + 4 + tig];
                    if ((ks & 1) == 0) {
                        MMA_BF16(d0, d1, d2, d3, af[ks][0], af[ks][1], af[ks][2], af[ks][3], b0, b1);
                    } else {
                        MMA_BF16(e0, e1, e2, e3, af[ks][0], af[ks][1], af[ks][2], af[ks][3], b0, b1);
                    }
                }
                float v0 = ((d0 + e0) * 0.125f + cA[jj].x) * mult;
                float v1 = ((d1 + e1) * 0.125f + cA[jj].y) * mult;
                float v2 = ((d2 + e2) * 0.125f + cB[jj].x) * mult;
                float v3 = ((d3 + e3) * 0.125f + cB[jj].y) * mult;

                float pmA = fmaxf(v0, v1);
                float pmB = fmaxf(v2, v3);

                if (pmA > mA - 88.0f) {
                    float mn = fmaxf(mA, pmA);
                    sA = sA * __expf(mA - mn) + __expf(v0 - mn) + __expf(v1 - mn);
                    mA = mn;
                }
                if (pmB > mB - 88.0f) {
                    float mn = fmaxf(mB, pmB);
                    sB = sB * __expf(mB - mn) + __expf(v2 - mn) + __expf(v3 - mn);
                    mB = mn;
                }
            }
        }
        __syncthreads();
    }

#pragma unroll
    for (int off = 1; off < 4; off <<= 1) {
        float om = __shfl_xor_sync(0xffffffffu, mA, off);
        float os = __shfl_xor_sync(0xffffffffu, sA, off);
        float mn = fmaxf(mA, om);
        sA = sA * __expf(mA - mn) + os * __expf(om - mn);
        mA = mn;

        om = __shfl_xor_sync(0xffffffffu, mB, off);
        os = __shfl_xor_sync(0xffffffffu, sB, off);
        mn = fmaxf(mB, om);
        sB = sB * __expf(mB - mn) + os * __expf(om - mn);
        mB = mn;
    }

    if (tig == 0) {
        g_part[rA * NCHUNK + chunk] = make_float2(mA, sA);
        g_part[rB * NCHUNK + chunk] = make_float2(mB, sB);
    }
}

// ---------------------------------------------------------------------------
// Kernel 4 (fallback): out pass, gated. grid (4, NGRAPH), 256 threads.
// ---------------------------------------------------------------------------
__global__ __launch_bounds__(256) void out_kernel(const float* __restrict__ bmat,
                                                  float* __restrict__ out)
{
    if (g_flagcnt[blockIdx.y] == 0) return;

    extern __shared__ float smf[];
    float* Qs = smf;                  // 32 x 68
    float* Ks = Qs + 32 * 68;         // 128 x 68
    float* Vs = Ks + BLK * 68;        // 128 x 64
    float* Ps = Vs + BLK * 64;        // 32 x 132
    __shared__ float sm_m[32], sm_is[32];

    int g    = blockIdx.y;
    int qd   = blockIdx.x;
    int tid  = threadIdx.x;
    int base = g * BLK;
    int r0g  = base + qd * 32;

    for (int idx = tid; idx < 32 * DQ; idx += 256) {
        int r = idx >> 6, c = idx & 63;
        Qs[r * 68 + c] = g_Qf[(size_t)(r0g + r) * DQ + c];
    }
    for (int idx = tid; idx < BLK * DQ; idx += 256) {
        int r = idx >> 6, c = idx & 63;
        Ks[r * 68 + c] = g_Kf[(size_t)(base + r) * DQ + c];
        Vs[r * 64 + c] = g_Vf[(size_t)(base + r) * DQ + c];
    }
    if (tid < 32) {
        float m = neg_inf_f(), s = 0.0f;
#pragma unroll
        for (int ch = 0; ch < NCHUNK; ch++) {
            float2 p = g_part[(size_t)(r0g + tid) * NCHUNK + ch];
            float mn = fmaxf(m, p.x);
            s = s * __expf(m - mn) + p.y * __expf(p.x - mn);
            m = mn;
        }
        sm_m[tid]  = m;
        sm_is[tid] = 1.0f / s;
    }
    __syncthreads();

    {
        int r  = tid >> 3;
        int l8 = tid & 7;
        float acc[16];
#pragma unroll
        for (int j = 0; j < 16; j++) acc[j] = 0.0f;

#pragma unroll 4
        for (int k = 0; k < DQ; k += 4) {
            float4 q4 = *reinterpret_cast<const float4*>(&Qs[r * 68 + k]);
#pragma unroll
            for (int j = 0; j < 16; j++) {
                int c = l8 + j * 8;
                float4 k4 = *reinterpret_cast<const float4*>(&Ks[c * 68 + k]);
                acc[j] = fmaf(q4.x, k4.x, acc[j]);
                acc[j] = fmaf(q4.y, k4.y, acc[j]);
                acc[j] = fmaf(q4.z, k4.z, acc[j]);
                acc[j] = fmaf(q4.w, k4.w, acc[j]);
            }
        }
        float m  = sm_m[r];
        float is = sm_is[r];
        const float* brow = bmat + (size_t)(r0g + r) * NTOT + base;
#pragma unroll
        for (int j = 0; j < 16; j++) {
            int c = l8 + j * 8;
            float v = acc[j] * 0.125f + brow[c];
            Ps[r * 132 + c] = __expf(v - m) * is;
        }
    }
    __syncthreads();

    {
        int d  = tid & 63;
        int rg = tid >> 6;
#pragma unroll
        for (int rr = 0; rr < 8; rr++) {
            int r = rg * 8 + rr;
            float a = 0.0f;
#pragma unroll 8
            for (int j = 0; j < BLK; j += 4) {
                float4 p = *reinterpret_cast<const float4*>(&Ps[r * 132 + j]);
                a = fmaf(p.x, Vs[(j + 0) * 64 + d], a);
                a = fmaf(p.y, Vs[(j + 1) * 64 + d], a);
                a = fmaf(p.z, Vs[(j + 2) * 64 + d], a);
                a = fmaf(p.w, Vs[(j + 3) * 64 + d], a);
            }
            out[(size_t)(r0g + r) * DQ + d] = a;
        }
    }
}

// ---------------------------------------------------------------------------
extern "C" void kernel_launch(void* const* d_in, const int* in_sizes, int n_in,
                              void* d_out, int out_size)
{
    const float* query = (const float*)d_in[0];
    const float* key   = (const float*)d_in[1];
    const float* value = (const float*)d_in[2];
    const float* bmat  = (const float*)d_in[3];
    // d_in[4] = ptr (int32): fixed uniform 128-node segments (arange(65)*128).
    const float* Wq = (const float*)d_in[5];
    const float* bq = (const float*)d_in[6];
    const float* Wk = (const float*)d_in[7];
    const float* bk = (const float*)d_in[8];
    const float* Wv = (const float*)d_in[9];
    const float* bv = (const float*)d_in[10];
    float* out = (float*)d_out;

    const int SMEM3 = (32 * 68 + BLK * 68 + BLK * 64 + 32 * 132) * (int)sizeof(float);
    cudaFuncSetAttribute(out_kernel, cudaFuncAttributeMaxDynamicSharedMemorySize, SMEM3);

    wt_kernel<<<3, 256>>>(Wq, Wk, Wv);
    proj_mma_kernel<<<dim3(NTOT / PROWS, 3), 128>>>(query, key, value, bq, bk, bv);
    screen_kernel<<<NGRAPH, 256>>>(bmat, out);
    stats_kernel<<<dim3(NCHUNK, NGRAPH), 256>>>(bmat);
    out_kernel<<<dim3(4, NGRAPH), 256, SMEM3>>>(bmat, out);
}

// round 6
// speedup vs baseline: 5.5192x; 1.1429x over previous
#include <cuda_runtime.h>
#include <cuda_bf16.h>
#include <cstdint>
#include <cstddef>

// GraphormerAttentionHead: N=8192, 64 graphs x 128 nodes, D_in=128, D=64.
// a = (q k^T / 8 + b) * (in_block ? 1 : -1e6); softmax over FULL row; * in_block; @ v.
//
// Exact-arithmetic screen: the row max m comes from out-of-block terms
// -1e6*(a+b) (~ +2.5e6). If a LOWER bound on m (from a 128-col out-of-block
// sample tile) exceeds the in-block max by >= 3e5 (margin >> the fp32 exp
// underflow bound 105 plus all bf16/projection error bounds ~1e5), every
// in-block expf(v-m) is EXACTLY +0.0f, so the output rows are exactly zero.
// screen_kernel writes the zeros and flags any graph that fails the test;
// fallback_kernel (gated, normally exits immediately) recomputes flagged
// graphs with the honest full-row softmax.

#define NTOT   8192
#define NGRAPH 64
#define BLK    128
#define DIN    128
#define DQ     64

__device__ float          g_Qf[NTOT * DQ];
__device__ float          g_Kf[NTOT * DQ];
__device__ float          g_Vf[NTOT * DQ];
__device__ __nv_bfloat16  g_Qh[NTOT * DQ];
__device__ __nv_bfloat16  g_Kh[NTOT * DQ];
__device__ uint32_t       g_Wth[3 * DQ * (DIN / 2)];   // bf16x2, [mat][n][k/2]
__device__ int            g_flagcnt[NGRAPH];           // rows needing full path

__device__ __forceinline__ float neg_inf_f() { return __int_as_float(0xff800000u); }

__device__ __forceinline__ uint32_t pack_bf16x2(float lo, float hi) {
    __nv_bfloat162 h = __floats2bfloat162_rn(lo, hi);
    return *reinterpret_cast<uint32_t*>(&h);
}

#define MMA_BF16(c0,c1,c2,c3,a0,a1,a2,a3,b0,b1)                                  \
    asm volatile(                                                                \
        "mma.sync.aligned.m16n8k16.row.col.f32.bf16.bf16.f32 "                   \
        "{%0,%1,%2,%3}, {%4,%5,%6,%7}, {%8,%9}, {%0,%1,%2,%3};\n"                \
        : "+f"(c0), "+f"(c1), "+f"(c2), "+f"(c3)                                 \
        : "r"(a0), "r"(a1), "r"(a2), "r"(a3), "r"(b0), "r"(b1))

// ---------------------------------------------------------------------------
// Kernel 0: W [128k x 64n] fp32 -> g_Wth [n][k/2] bf16x2; zero flags.
// ---------------------------------------------------------------------------
__global__ __launch_bounds__(256) void wt_kernel(
    const float* __restrict__ Wq, const float* __restrict__ Wk,
    const float* __restrict__ Wv)
{
    __shared__ float Wsm[DIN * 65];
    int mat = blockIdx.x;
    const float* W = (mat == 0) ? Wq : (mat == 1) ? Wk : Wv;
    int tid = threadIdx.x;

    if (mat == 0 && tid < NGRAPH) g_flagcnt[tid] = 0;

    for (int idx = tid; idx < DIN * DQ; idx += 256) {
        int k = idx >> 6, n = idx & 63;
        Wsm[k * 65 + n] = W[idx];
    }
    __syncthreads();

    uint32_t* dst = g_Wth + mat * DQ * (DIN / 2);
    for (int idx = tid; idx < DQ * (DIN / 2); idx += 256) {
        int n = idx >> 6, kp = idx & 63;
        dst[idx] = pack_bf16x2(Wsm[(2 * kp) * 65 + n], Wsm[(2 * kp + 1) * 65 + n]);
    }
}

// ---------------------------------------------------------------------------
// Kernel 1: Y = X @ W + bias via bf16 mma.sync. grid (64, 3), 256 threads.
// Each CTA: 128 rows x 64 cols x K=128 (8 warps x 16 rows).
// ---------------------------------------------------------------------------
__global__ __launch_bounds__(256) void proj_mma_kernel(
    const float* __restrict__ query, const float* __restrict__ key,
    const float* __restrict__ value,
    const float* __restrict__ bq, const float* __restrict__ bk,
    const float* __restrict__ bv)
{
    __shared__ uint32_t Xs[BLK * 68];
    __shared__ uint32_t Wt[DQ * 68];
    __shared__ float    bs[DQ];

    int mat = blockIdx.y;
    const float* X    = (mat == 0) ? query : (mat == 1) ? key : value;
    const float* bias = (mat == 0) ? bq    : (mat == 1) ? bk  : bv;
    float* Yf         = (mat == 0) ? g_Qf  : (mat == 1) ? g_Kf : g_Vf;
    __nv_bfloat16* Yh = (mat == 0) ? g_Qh  : (mat == 1) ? g_Kh : nullptr;

    int tid  = threadIdx.x;
    int row0 = blockIdx.x * BLK;

    const uint32_t* wsrc = g_Wth + mat * DQ * (DIN / 2);
    for (int idx = tid; idx < DQ * (DIN / 2); idx += 256) {
        int n = idx >> 6, kp = idx & 63;
        Wt[n * 68 + kp] = wsrc[idx];
    }
    if (tid < DQ) bs[tid] = bias[tid];

    for (int idx = tid; idx < BLK * DIN / 4; idx += 256) {
        int r  = idx >> 5;
        int c4 = (idx & 31) * 4;
        float4 xv = *reinterpret_cast<const float4*>(X + (size_t)(row0 + r) * DIN + c4);
        Xs[r * 68 + (c4 >> 1)]     = pack_bf16x2(xv.x, xv.y);
        Xs[r * 68 + (c4 >> 1) + 1] = pack_bf16x2(xv.z, xv.w);
    }
    __syncthreads();

    int w   = tid >> 5;
    int l   = tid & 31;
    int gid = l >> 2;
    int tig = l & 3;
    int rAl = w * 16 + gid;
    int rBl = rAl + 8;

    float acc[8][4];
#pragma unroll
    for (int nt = 0; nt < 8; nt++)
#pragma unroll
        for (int j = 0; j < 4; j++) acc[nt][j] = 0.0f;

#pragma unroll
    for (int ks = 0; ks < 8; ks++) {
        uint32_t a0 = Xs[rAl * 68 + ks * 8 + tig];
        uint32_t a1 = Xs[rBl * 68 + ks * 8 + tig];
        uint32_t a2 = Xs[rAl * 68 + ks * 8 + 4 + tig];
        uint32_t a3 = Xs[rBl * 68 + ks * 8 + 4 + tig];
#pragma unroll
        for (int nt = 0; nt < 8; nt++) {
            uint32_t b0 = Wt[(nt * 8 + gid) * 68 + ks * 8 + tig];
            uint32_t b1 = Wt[(nt * 8 + gid) * 68 + ks * 8 + 4 + tig];
            MMA_BF16(acc[nt][0], acc[nt][1], acc[nt][2], acc[nt][3],
                     a0, a1, a2, a3, b0, b1);
        }
    }

    int rowA = row0 + rAl;
    int rowB = row0 + rBl;
#pragma unroll
    for (int nt = 0; nt < 8; nt++) {
        int col = nt * 8 + tig * 2;
        float bx = bs[col], by = bs[col + 1];
        float o0 = acc[nt][0] + bx, o1 = acc[nt][1] + by;
        float o2 = acc[nt][2] + bx, o3 = acc[nt][3] + by;
        *reinterpret_cast<float2*>(&Yf[(size_t)rowA * DQ + col]) = make_float2(o0, o1);
        *reinterpret_cast<float2*>(&Yf[(size_t)rowB * DQ + col]) = make_float2(o2, o3);
        if (Yh != nullptr) {
            uint32_t* yh32 = reinterpret_cast<uint32_t*>(Yh);
            yh32[rowA * 32 + (col >> 1)] = pack_bf16x2(o0, o1);
            yh32[rowB * 32 + (col >> 1)] = pack_bf16x2(o2, o3);
        }
    }
}

// ---------------------------------------------------------------------------
// Kernel 2: screen. grid = (2, NGRAPH), 128 threads (4 warps x 16 rows).
// CTA (h, g) handles rows [g*128 + h*64, +64): computes in-block max vi and
// sample-tile lower bound m_lb; writes provably-exact zero output rows;
// flags graphs needing the full path.
// ---------------------------------------------------------------------------
__global__ __launch_bounds__(128) void screen_kernel(const float* __restrict__ bmat,
                                                     float* __restrict__ out)
{
    __shared__ uint32_t Ki[BLK * 36];    // in-block K tile (bf16x2, stride 36)
    __shared__ uint32_t Ksm[BLK * 36];   // sample K tile

    const uint32_t* Qh32 = reinterpret_cast<const uint32_t*>(g_Qh);
    const uint32_t* Kh32 = reinterpret_cast<const uint32_t*>(g_Kh);

    int g    = blockIdx.y;
    int h    = blockIdx.x;
    int tid  = threadIdx.x;
    int w    = tid >> 5;
    int l    = tid & 31;
    int gid  = l >> 2;
    int tig  = l & 3;
    int base  = g * BLK;
    int sbase = ((g + 1) & (NGRAPH - 1)) * BLK;   // out-of-block sample columns
    int rbase = base + h * 64;

    int rA = rbase + w * 16 + gid;
    int rB = rA + 8;

    for (int idx = tid; idx < BLK * 32; idx += 128) {
        int rr = idx >> 5, cw = idx & 31;
        Ki[rr * 36 + cw]  = Kh32[(size_t)(base + rr) * 32 + cw];
        Ksm[rr * 36 + cw] = Kh32[(size_t)(sbase + rr) * 32 + cw];
    }

    // zero output rows (exact result for unflagged graphs; flagged graphs
    // fully overwritten by fallback_kernel).
    for (int idx = tid; idx < 64 * DQ / 4; idx += 128) {
        int r = idx >> 4, c4 = (idx & 15) * 4;
        *reinterpret_cast<float4*>(&out[(size_t)(rbase + r) * DQ + c4]) =
            make_float4(0.f, 0.f, 0.f, 0.f);
    }

    uint32_t af[4][4];
#pragma unroll
    for (int ks = 0; ks < 4; ks++) {
        af[ks][0] = Qh32[rA * 32 + ks * 8 + tig];
        af[ks][1] = Qh32[rB * 32 + ks * 8 + tig];
        af[ks][2] = Qh32[rA * 32 + ks * 8 + 4 + tig];
        af[ks][3] = Qh32[rB * 32 + ks * 8 + 4 + tig];
    }
    __syncthreads();

    float viA = neg_inf_f(), viB = neg_inf_f();
    float vsA = neg_inf_f(), vsB = neg_inf_f();

    const float* biA = bmat + (size_t)rA * NTOT + base  + tig * 2;
    const float* biB = bmat + (size_t)rB * NTOT + base  + tig * 2;
    const float* bsA = bmat + (size_t)rA * NTOT + sbase + tig * 2;
    const float* bsB = bmat + (size_t)rB * NTOT + sbase + tig * 2;

#pragma unroll 4
    for (int n8 = 0; n8 < 16; n8++) {
        int krow = (n8 * 8 + gid) * 36;
        {
            float c0 = 0.f, c1 = 0.f, c2 = 0.f, c3 = 0.f;
#pragma unroll
            for (int ks = 0; ks < 4; ks++) {
                uint32_t b0 = Ki[krow + ks * 8 + tig];
                uint32_t b1 = Ki[krow + ks * 8 + 4 + tig];
                MMA_BF16(c0, c1, c2, c3, af[ks][0], af[ks][1], af[ks][2], af[ks][3], b0, b1);
            }
            float2 bA = *reinterpret_cast<const float2*>(biA + n8 * 8);
            float2 bB = *reinterpret_cast<const float2*>(biB + n8 * 8);
            viA = fmaxf(viA, fmaxf(c0 * 0.125f + bA.x, c1 * 0.125f + bA.y));
            viB = fmaxf(viB, fmaxf(c2 * 0.125f + bB.x, c3 * 0.125f + bB.y));
        }
        {
            float c0 = 0.f, c1 = 0.f, c2 = 0.f, c3 = 0.f;
#pragma unroll
            for (int ks = 0; ks < 4; ks++) {
                uint32_t b0 = Ksm[krow + ks * 8 + tig];
                uint32_t b1 = Ksm[krow + ks * 8 + 4 + tig];
                MMA_BF16(c0, c1, c2, c3, af[ks][0], af[ks][1], af[ks][2], af[ks][3], b0, b1);
            }
            float2 bA = *reinterpret_cast<const float2*>(bsA + n8 * 8);
            float2 bB = *reinterpret_cast<const float2*>(bsB + n8 * 8);
            vsA = fmaxf(vsA, fmaxf((c0 * 0.125f + bA.x) * -1000000.0f,
                                   (c1 * 0.125f + bA.y) * -1000000.0f));
            vsB = fmaxf(vsB, fmaxf((c2 * 0.125f + bB.x) * -1000000.0f,
                                   (c3 * 0.125f + bB.y) * -1000000.0f));
        }
    }

#pragma unroll
    for (int off = 1; off < 4; off <<= 1) {
        viA = fmaxf(viA, __shfl_xor_sync(0xffffffffu, viA, off));
        viB = fmaxf(viB, __shfl_xor_sync(0xffffffffu, viB, off));
        vsA = fmaxf(vsA, __shfl_xor_sync(0xffffffffu, vsA, off));
        vsB = fmaxf(vsB, __shfl_xor_sync(0xffffffffu, vsB, off));
    }

    if (tig == 0) {
        const float MARGIN = 300000.0f;
        if (!(vsA >= viA + MARGIN)) atomicAdd(&g_flagcnt[g], 1);
        if (!(vsB >= viB + MARGIN)) atomicAdd(&g_flagcnt[g], 1);
    }
}

// ---------------------------------------------------------------------------
// Kernel 3 (fallback, gated): full per-graph recompute. grid = NGRAPH,
// 256 threads, ~170KB dyn smem. Normally every CTA exits on the flag read.
// Phase A: stream all 8192 columns -> per-row (m, 1/s).
// Phase B: in-block probabilities (fp32 q/k) -> P @ V -> out.
// ---------------------------------------------------------------------------
__global__ __launch_bounds__(256) void fallback_kernel(const float* __restrict__ bmat,
                                                       float* __restrict__ out)
{
    if (g_flagcnt[blockIdx.x] == 0) return;

    extern __shared__ float smf[];
    __shared__ float sm_m[BLK], sm_is[BLK];

    const uint32_t* Qh32 = reinterpret_cast<const uint32_t*>(g_Qh);
    const uint32_t* Kh32 = reinterpret_cast<const uint32_t*>(g_Kh);

    int g    = blockIdx.x;
    int tid  = threadIdx.x;
    int w    = tid >> 5;
    int l    = tid & 31;
    int gid  = l >> 2;
    int tig  = l & 3;
    int base = g * BLK;

    // ---------------- Phase A: (m, s) over all 8192 columns ----------------
    {
        uint32_t* Kst = reinterpret_cast<uint32_t*>(smf);   // BLK*36 u32

        int rA = base + w * 16 + gid;
        int rB = rA + 8;

        uint32_t af[4][4];
#pragma unroll
        for (int ks = 0; ks < 4; ks++) {
            af[ks][0] = Qh32[rA * 32 + ks * 8 + tig];
            af[ks][1] = Qh32[rB * 32 + ks * 8 + tig];
            af[ks][2] = Qh32[rA * 32 + ks * 8 + 4 + tig];
            af[ks][3] = Qh32[rB * 32 + ks * 8 + 4 + tig];
        }

        float mA = neg_inf_f(), sA = 0.0f;
        float mB = neg_inf_f(), sB = 0.0f;

        for (int sub = 0; sub < NTOT / BLK; sub++) {
            int j0 = sub * BLK;

            __syncthreads();
            for (int idx = tid; idx < BLK * 32; idx += 256) {
                int rr = idx >> 5, cw = idx & 31;
                Kst[rr * 36 + cw] = Kh32[(size_t)(j0 + rr) * 32 + cw];
            }
            __syncthreads();

            float mult = (sub == g) ? 1.0f : -1000000.0f;
            const float* brA = bmat + (size_t)rA * NTOT + j0 + tig * 2;
            const float* brB = bmat + (size_t)rB * NTOT + j0 + tig * 2;

#pragma unroll 4
            for (int n8 = 0; n8 < 16; n8++) {
                int krow = (n8 * 8 + gid) * 36;
                float c0 = 0.f, c1 = 0.f, c2 = 0.f, c3 = 0.f;
#pragma unroll
                for (int ks = 0; ks < 4; ks++) {
                    uint32_t b0 = Kst[krow + ks * 8 + tig];
                    uint32_t b1 = Kst[krow + ks * 8 + 4 + tig];
                    MMA_BF16(c0, c1, c2, c3,
                             af[ks][0], af[ks][1], af[ks][2], af[ks][3], b0, b1);
                }
                float2 bA = *reinterpret_cast<const float2*>(brA + n8 * 8);
                float2 bB = *reinterpret_cast<const float2*>(brB + n8 * 8);

                float v0 = (c0 * 0.125f + bA.x) * mult;
                float v1 = (c1 * 0.125f + bA.y) * mult;
                float v2 = (c2 * 0.125f + bB.x) * mult;
                float v3 = (c3 * 0.125f + bB.y) * mult;

                float pmA = fmaxf(v0, v1);
                float pmB = fmaxf(v2, v3);
                if (pmA > mA - 88.0f) {
                    float mn = fmaxf(mA, pmA);
                    sA = sA * __expf(mA - mn) + __expf(v0 - mn) + __expf(v1 - mn);
                    mA = mn;
                }
                if (pmB > mB - 88.0f) {
                    float mn = fmaxf(mB, pmB);
                    sB = sB * __expf(mB - mn) + __expf(v2 - mn) + __expf(v3 - mn);
                    mB = mn;
                }
            }
        }

#pragma unroll
        for (int off = 1; off < 4; off <<= 1) {
            float om = __shfl_xor_sync(0xffffffffu, mA, off);
            float os = __shfl_xor_sync(0xffffffffu, sA, off);
            float mn = fmaxf(mA, om);
            sA = sA * __expf(mA - mn) + os * __expf(om - mn);
            mA = mn;

            om = __shfl_xor_sync(0xffffffffu, mB, off);
            os = __shfl_xor_sync(0xffffffffu, sB, off);
            mn = fmaxf(mB, om);
            sB = sB * __expf(mB - mn) + os * __expf(om - mn);
            mB = mn;
        }

        if (tig == 0) {
            sm_m[w * 16 + gid]      = mA;
            sm_is[w * 16 + gid]     = 1.0f / sA;
            sm_m[w * 16 + gid + 8]  = mB;
            sm_is[w * 16 + gid + 8] = 1.0f / sB;
        }
        __syncthreads();
    }

    // ---------------- Phase B: in-block probabilities, P @ V ----------------
    float* Qs  = smf;                 // 128 x 68
    float* Kss = Qs  + BLK * 68;      // 128 x 68
    float* Vs  = Kss + BLK * 68;      // 128 x 64
    float* Ps  = Vs  + BLK * 64;      // 128 x 132

    for (int idx = tid; idx < BLK * DQ; idx += 256) {
        int r = idx >> 6, c = idx & 63;
        Qs[r * 68 + c]  = g_Qf[(size_t)(base + r) * DQ + c];
        Kss[r * 68 + c] = g_Kf[(size_t)(base + r) * DQ + c];
        Vs[r * 64 + c]  = g_Vf[(size_t)(base + r) * DQ + c];
    }
    __syncthreads();

    for (int it = 0; it < 4; it++) {
        int tt = it * 256 + tid;
        int r0 = (tt >> 5) * 4;
        int j0 = (tt & 31) * 4;
        float acc[4][4];
#pragma unroll
        for (int i = 0; i < 4; i++)
#pragma unroll
            for (int j = 0; j < 4; j++) acc[i][j] = 0.0f;

        for (int k = 0; k < DQ; k += 4) {
            float4 q4[4], k4[4];
#pragma unroll
            for (int i = 0; i < 4; i++)
                q4[i] = *reinterpret_cast<const float4*>(&Qs[(r0 + i) * 68 + k]);
#pragma unroll
            for (int j = 0; j < 4; j++)
                k4[j] = *reinterpret_cast<const float4*>(&Kss[(j0 + j) * 68 + k]);
#pragma unroll
            for (int i = 0; i < 4; i++)
#pragma unroll
                for (int j = 0; j < 4; j++) {
                    acc[i][j] = fmaf(q4[i].x, k4[j].x, acc[i][j]);
                    acc[i][j] = fmaf(q4[i].y, k4[j].y, acc[i][j]);
                    acc[i][j] = fmaf(q4[i].z, k4[j].z, acc[i][j]);
                    acc[i][j] = fmaf(q4[i].w, k4[j].w, acc[i][j]);
                }
        }
#pragma unroll
        for (int i = 0; i < 4; i++) {
            int r = r0 + i;
            float m  = sm_m[r];
            float is = sm_is[r];
#pragma unroll
            for (int j = 0; j < 4; j++) {
                int jj = j0 + j;
                float v = acc[i][j] * 0.125f +
                          bmat[(size_t)(base + r) * NTOT + base + jj];
                Ps[r * 132 + jj] = __expf(v - m) * is;
            }
        }
    }
    __syncthreads();

    int d  = tid & 63;
    int rb = tid >> 6;
    for (int r0 = rb * 4; r0 < BLK; r0 += 16) {
        float a0 = 0.f, a1 = 0.f, a2 = 0.f, a3 = 0.f;
        for (int j = 0; j < BLK; j += 4) {
            float4 p0 = *reinterpret_cast<const float4*>(&Ps[(r0 + 0) * 132 + j]);
            float4 p1 = *reinterpret_cast<const float4*>(&Ps[(r0 + 1) * 132 + j]);
            float4 p2 = *reinterpret_cast<const float4*>(&Ps[(r0 + 2) * 132 + j]);
            float4 p3 = *reinterpret_cast<const float4*>(&Ps[(r0 + 3) * 132 + j]);
            float v0 = Vs[(j + 0) * 64 + d];
            float v1 = Vs[(j + 1) * 64 + d];
            float v2 = Vs[(j + 2) * 64 + d];
            float v3 = Vs[(j + 3) * 64 + d];
            a0 += p0.x * v0 + p0.y * v1 + p0.z * v2 + p0.w * v3;
            a1 += p1.x * v0 + p1.y * v1 + p1.z * v2 + p1.w * v3;
            a2 += p2.x * v0 + p2.y * v1 + p2.z * v2 + p2.w * v3;
            a3 += p3.x * v0 + p3.y * v1 + p3.z * v2 + p3.w * v3;
        }
        out[(size_t)(base + r0 + 0) * DQ + d] = a0;
        out[(size_t)(base + r0 + 1) * DQ + d] = a1;
        out[(size_t)(base + r0 + 2) * DQ + d] = a2;
        out[(size_t)(base + r0 + 3) * DQ + d] = a3;
    }
}

// ---------------------------------------------------------------------------
extern "C" void kernel_launch(void* const* d_in, const int* in_sizes, int n_in,
                              void* d_out, int out_size)
{
    const float* query = (const float*)d_in[0];
    const float* key   = (const float*)d_in[1];
    const float* value = (const float*)d_in[2];
    const float* bmat  = (const float*)d_in[3];
    // d_in[4] = ptr (int32): fixed uniform 128-node segments (arange(65)*128).
    const float* Wq = (const float*)d_in[5];
    const float* bq = (const float*)d_in[6];
    const float* Wk = (const float*)d_in[7];
    const float* bk = (const float*)d_in[8];
    const float* Wv = (const float*)d_in[9];
    const float* bv = (const float*)d_in[10];
    float* out = (float*)d_out;

    const int SMEMF = (BLK * 68 * 2 + BLK * 64 + BLK * 132) * (int)sizeof(float); // 169984
    cudaFuncSetAttribute(fallback_kernel, cudaFuncAttributeMaxDynamicSharedMemorySize, SMEMF);

    wt_kernel<<<3, 256>>>(Wq, Wk, Wv);
    proj_mma_kernel<<<dim3(NTOT / BLK, 3), 256>>>(query, key, value, bq, bk, bv);
    screen_kernel<<<dim3(2, NGRAPH), 128>>>(bmat, out);
    fallback_kernel<<<NGRAPH, 256, SMEMF>>>(bmat, out);
}